// round 3
// baseline (speedup 1.0000x reference)
#include <cuda_runtime.h>
#include <mma.h>
#include <math.h>

using namespace nvcuda;

#define NN    512
#define MEM   1024
#define KD    1024
#define TM3   3072
#define NINT  128
#define IBASE 384
#define NLVL  5

// ---------------- scratch (static device allocation, allowed) ----------------
__device__ float g_XI [NN * TM3];     // x @ ioux_w^T + ioux_b   (all nodes)
__device__ float g_XF [NINT * MEM];   // x @ fx_w^T + fx_b       (internal only)
__device__ float g_c  [NN * MEM];     // cell states
__device__ float g_FH [NN * MEM];     // h @ fh_w^T + fh_b       (all nodes)
__device__ float g_hs [NINT * MEM];   // child-sum of h
__device__ float g_t  [NINT * MEM];   // W_rel-transformed child-sum
__device__ float g_fc [NINT * MEM];   // sum_k f_k * c_k
__device__ float g_IOU[64 * TM3];     // per-level iou delta (incl. iouh_b)
__device__ int   g_grp_nodes[NLVL][64];   // li per level, sorted by rel
__device__ int   g_grp_start[NLVL][50];

__device__ __forceinline__ float sigm(float v) { return 1.0f / (1.0f + expf(-v)); }

// ============ tf32 GEMM: C[m,n] = sum_k A[m,k]*B[n,k] + bias[n] ==============
// BM=BN=64, BK=32. 128 threads = 4 warps (2x2), each warp 32x32 via 2x2 wmma.
// M may be ragged (guarded loads + guarded stores). N, K multiples of 64.
__global__ void __launch_bounds__(128) gemm_tf32(const float* __restrict__ A,
                                                 const float* __restrict__ B,
                                                 const float* __restrict__ bias,
                                                 float* __restrict__ C,
                                                 int M, int N, int K)
{
    __shared__ float As[64 * 40];
    __shared__ float Bs[64 * 40];
    __shared__ float Cs[4][16 * 20];

    int tid  = threadIdx.x;
    int lane = tid & 31, wid = tid >> 5;
    int wm = wid >> 1, wn = wid & 1;
    int m0 = blockIdx.y * 64, n0 = blockIdx.x * 64;

    wmma::fragment<wmma::accumulator, 16, 16, 8, float> acc[2][2];
    #pragma unroll
    for (int i = 0; i < 2; i++)
        #pragma unroll
        for (int j = 0; j < 2; j++)
            wmma::fill_fragment(acc[i][j], 0.0f);

    for (int k0 = 0; k0 < K; k0 += 32) {
        // load A tile 64x32 (guarded on M) and B tile 64x32
        #pragma unroll
        for (int i = 0; i < 4; i++) {
            int e = i * 128 + tid;          // 512 float4 slots
            int r = e >> 3, c4 = (e & 7) * 4;
            int gm = m0 + r;
            float4 va = make_float4(0.f, 0.f, 0.f, 0.f);
            if (gm < M) va = *(const float4*)(A + (size_t)gm * K + k0 + c4);
            As[r * 40 + c4 + 0] = va.x; As[r * 40 + c4 + 1] = va.y;
            As[r * 40 + c4 + 2] = va.z; As[r * 40 + c4 + 3] = va.w;
            float4 vb = *(const float4*)(B + (size_t)(n0 + r) * K + k0 + c4);
            Bs[r * 40 + c4 + 0] = vb.x; Bs[r * 40 + c4 + 1] = vb.y;
            Bs[r * 40 + c4 + 2] = vb.z; Bs[r * 40 + c4 + 3] = vb.w;
        }
        __syncthreads();
        #pragma unroll
        for (int kk = 0; kk < 4; kk++) {
            wmma::fragment<wmma::matrix_a, 16, 16, 8, wmma::precision::tf32, wmma::row_major> af[2];
            wmma::fragment<wmma::matrix_b, 16, 16, 8, wmma::precision::tf32, wmma::col_major> bf[2];
            #pragma unroll
            for (int i = 0; i < 2; i++) {
                wmma::load_matrix_sync(af[i], &As[(wm * 32 + i * 16) * 40 + kk * 8], 40);
                #pragma unroll
                for (int t = 0; t < af[i].num_elements; t++)
                    af[i].x[t] = wmma::__float_to_tf32(af[i].x[t]);
            }
            #pragma unroll
            for (int j = 0; j < 2; j++) {
                wmma::load_matrix_sync(bf[j], &Bs[(wn * 32 + j * 16) * 40 + kk * 8], 40);
                #pragma unroll
                for (int t = 0; t < bf[j].num_elements; t++)
                    bf[j].x[t] = wmma::__float_to_tf32(bf[j].x[t]);
            }
            #pragma unroll
            for (int i = 0; i < 2; i++)
                #pragma unroll
                for (int j = 0; j < 2; j++)
                    wmma::mma_sync(acc[i][j], af[i], bf[j], acc[i][j]);
        }
        __syncthreads();
    }

    // epilogue: per-warp staging + guarded store
    #pragma unroll
    for (int i = 0; i < 2; i++)
        #pragma unroll
        for (int j = 0; j < 2; j++) {
            wmma::store_matrix_sync(Cs[wid], acc[i][j], 20, wmma::mem_row_major);
            __syncwarp();
            #pragma unroll
            for (int e = 0; e < 8; e++) {
                int idx = lane + e * 32;           // 0..255
                int rr = idx >> 4, cc = idx & 15;
                int gm = m0 + wm * 32 + i * 16 + rr;
                int gn = n0 + wn * 32 + j * 16 + cc;
                if (gm < M)
                    C[(size_t)gm * N + gn] = Cs[wid][rr * 20 + cc] + bias[gn];
            }
            __syncwarp();
        }
}

// ---------------- leaves: nodes 0..383, pure elementwise from XI -------------
__global__ void leaf_k(float* __restrict__ h, const float* __restrict__ iouh_b)
{
    int node = blockIdx.y;
    int j = blockIdx.x * 256 + threadIdx.x;
    const float* xi = g_XI + (size_t)node * TM3;
    float ig = sigm(xi[j] + iouh_b[j]);
    float og = sigm(xi[MEM + j] + iouh_b[MEM + j]);
    float ug = tanhf(xi[2 * MEM + j] + iouh_b[2 * MEM + j]);
    float cv = ig * ug;
    g_c[(size_t)node * MEM + j] = cv;
    h[(size_t)node * MEM + j] = og * tanhf(cv);
}

// ---------------- one-time device-side grouping by relation ------------------
__global__ void prep_groups(const int* __restrict__ rel_ids)
{
    const int lvl_n0[NLVL]  = {384, 427, 491, 507, 511};
    const int lvl_cnt[NLVL] = { 43,  64,  16,   4,   1};
    for (int L = 0; L < NLVL; L++) {
        int cnt_r[49];
        for (int r = 0; r < 49; r++) cnt_r[r] = 0;
        int n0 = lvl_n0[L], cnt = lvl_cnt[L];
        for (int i = 0; i < cnt; i++) cnt_r[rel_ids[n0 + i]]++;
        int acc = 0;
        for (int r = 0; r < 49; r++) { g_grp_start[L][r] = acc; acc += cnt_r[r]; }
        g_grp_start[L][49] = acc;
        int pos[49];
        for (int r = 0; r < 49; r++) pos[r] = g_grp_start[L][r];
        for (int i = 0; i < cnt; i++) {
            int r = rel_ids[n0 + i];
            g_grp_nodes[L][pos[r]++] = n0 + i - IBASE;
        }
    }
}

// ---------------- child-sum of h for one level of internal nodes -------------
__global__ void csum_k(const float* __restrict__ h,
                       const int* __restrict__ child_idx, int n0)
{
    int node = n0 + blockIdx.y;
    int j = blockIdx.x * 256 + threadIdx.x;
    const int* ci = child_idx + node * 4;
    float s = 0.f;
    #pragma unroll
    for (int k = 0; k < 4; k++) {
        int c = ci[k];
        if (c >= 0) s += h[(size_t)c * MEM + j];
    }
    g_hs[(size_t)(node - IBASE) * MEM + j] = s;
}

// -------- t = hs @ Wrel[rel]^T, grouped by rel: W read once per group --------
__global__ void __launch_bounds__(256) wrel_grp(const float* __restrict__ Wrel, int lvl)
{
    int r  = blockIdx.y;                         // 0..48 (48 = identity / root)
    int s0 = g_grp_start[lvl][r];
    int g  = g_grp_start[lvl][r + 1] - s0;
    if (g == 0) return;
    __shared__ float sh[MEM];
    int lane = threadIdx.x & 31, wid = threadIdx.x >> 5;
    int row = blockIdx.x * 8 + wid;
    const float* W = Wrel + (size_t)r * (MEM * MEM) + (size_t)row * MEM;
    float4 w[8];
    #pragma unroll
    for (int i = 0; i < 8; i++) w[i] = *(const float4*)(W + (i * 32 + lane) * 4);
    for (int j = 0; j < g; j++) {
        int li = g_grp_nodes[lvl][s0 + j];
        for (int i = threadIdx.x; i < MEM / 4; i += 256)
            ((float4*)sh)[i] = ((const float4*)(g_hs + (size_t)li * MEM))[i];
        __syncthreads();
        float s = 0.f;
        #pragma unroll
        for (int i = 0; i < 8; i++) {
            int k4 = (i * 32 + lane) * 4;
            s += w[i].x * sh[k4] + w[i].y * sh[k4 + 1]
               + w[i].z * sh[k4 + 2] + w[i].w * sh[k4 + 3];
        }
        #pragma unroll
        for (int o = 16; o; o >>= 1) s += __shfl_xor_sync(0xffffffffu, s, o);
        if (lane == 0) g_t[(size_t)li * MEM + row] = s;
        __syncthreads();
    }
}

// ---- fc = sum_k sigm(FH[child_k] + xf) * c[child_k]  (pure elementwise) -----
__global__ void fc_k(const int* __restrict__ child_idx, int n0)
{
    int node = n0 + blockIdx.y;
    int li = node - IBASE;
    int j = blockIdx.x * 256 + threadIdx.x;
    const int* ci = child_idx + node * 4;
    float base = g_XF[(size_t)li * MEM + j];      // fh_b already inside g_FH
    float fc = 0.f;
    #pragma unroll
    for (int k = 0; k < 4; k++) {
        int c = ci[k];
        if (c >= 0)
            fc += sigm(g_FH[(size_t)c * MEM + j] + base) * g_c[(size_t)c * MEM + j];
    }
    g_fc[(size_t)li * MEM + j] = fc;
}

// -------- gates from IOU (= T@iouh_w^T + iouh_b) + XI + fc -> h, c -----------
__global__ void cell_k(float* __restrict__ h, int n0)
{
    int node = n0 + blockIdx.y;
    int li = node - IBASE;
    int j = blockIdx.x * 256 + threadIdx.x;
    const float* io = g_IOU + (size_t)blockIdx.y * TM3;
    const float* xi = g_XI + (size_t)node * TM3;
    float ig = sigm(io[j] + xi[j]);
    float og = sigm(io[MEM + j] + xi[MEM + j]);
    float ug = tanhf(io[2 * MEM + j] + xi[2 * MEM + j]);
    float cv = ig * ug + g_fc[(size_t)li * MEM + j];
    g_c[(size_t)node * MEM + j] = cv;
    h[(size_t)node * MEM + j] = og * tanhf(cv);
}

// ------------------------------- launcher ------------------------------------
extern "C" void kernel_launch(void* const* d_in, const int* in_sizes, int n_in,
                              void* d_out, int out_size)
{
    const float* x       = (const float*)d_in[0];
    const float* Wrel    = (const float*)d_in[1];
    const float* ioux_w  = (const float*)d_in[2];
    const float* ioux_b  = (const float*)d_in[3];
    const float* iouh_w  = (const float*)d_in[4];
    const float* iouh_b  = (const float*)d_in[5];
    const float* fx_w    = (const float*)d_in[6];
    const float* fx_b    = (const float*)d_in[7];
    const float* fh_w    = (const float*)d_in[8];
    const float* fh_b    = (const float*)d_in[9];
    const int*   child_idx = (const int*)d_in[10];
    const int*   rel_ids   = (const int*)d_in[11];
    float* h = (float*)d_out;

    float *p_XI, *p_XF, *p_FH, *p_t, *p_IOU;
    cudaGetSymbolAddress((void**)&p_XI,  g_XI);
    cudaGetSymbolAddress((void**)&p_XF,  g_XF);
    cudaGetSymbolAddress((void**)&p_FH,  g_FH);
    cudaGetSymbolAddress((void**)&p_t,   g_t);
    cudaGetSymbolAddress((void**)&p_IOU, g_IOU);

    prep_groups<<<1, 1>>>(rel_ids);

    // hoisted projections (tf32 tensor cores)
    gemm_tf32<<<dim3(TM3 / 64, NN / 64), 128>>>(x, ioux_w, ioux_b, p_XI, NN, TM3, KD);
    gemm_tf32<<<dim3(MEM / 64, 2), 128>>>(x + (size_t)IBASE * KD, fx_w, fx_b,
                                          p_XF, NINT, MEM, KD);

    // leaves + their forget-gate projection (needed by parents)
    leaf_k<<<dim3(4, 384), 256>>>(h, iouh_b);
    gemm_tf32<<<dim3(MEM / 64, 6), 128>>>(h, fh_w, fh_b, p_FH, 384, MEM, MEM);

    const int lvl_n0[NLVL]  = {384, 427, 491, 507, 511};
    const int lvl_cnt[NLVL] = { 43,  64,  16,   4,   1};
    for (int L = 0; L < NLVL; L++) {
        int n0 = lvl_n0[L], cnt = lvl_cnt[L];
        csum_k<<<dim3(4, cnt), 256>>>(h, child_idx, n0);
        wrel_grp<<<dim3(128, 49), 256>>>(Wrel, L);
        gemm_tf32<<<dim3(TM3 / 64, (cnt + 63) / 64), 128>>>(
            p_t + (size_t)(n0 - IBASE) * MEM, iouh_w, iouh_b, p_IOU, cnt, TM3, MEM);
        fc_k<<<dim3(4, cnt), 256>>>(child_idx, n0);
        cell_k<<<dim3(4, cnt), 256>>>(h, n0);
        if (L < NLVL - 1)  // root's FH never consumed
            gemm_tf32<<<dim3(MEM / 64, (cnt + 63) / 64), 128>>>(
                h + (size_t)n0 * MEM, fh_w, fh_b,
                p_FH + (size_t)n0 * MEM, cnt, MEM, MEM);
    }
}